// round 11
// baseline (speedup 1.0000x reference)
#include <cuda_runtime.h>
#include <math.h>

// ---------------------------------------------------------------------------
// ELA (JPEG quality-95 roundtrip error) fully fused per 16x16 tile.
// Input : float32 [B,256,256,3], B = in_sizes[0]/(256*256*3)
// Output: float32 [B,256,256,3]
// Dot scheme (identified by R7-R10 flip-rate algebra; measured p_flip = 0):
//   c_i = fma(a[i+4], b[i+4], a[i]*b[i]), i=0..3
//   result = (c0 + c1) + (c2 + c3)            (adjacent pairs, faddp-style)
// ---------------------------------------------------------------------------

__constant__ float cLUM[64] = {
    16, 11, 10, 16, 24, 40, 51, 61,
    12, 12, 14, 19, 26, 58, 60, 55,
    14, 13, 16, 24, 40, 57, 69, 56,
    14, 17, 22, 29, 51, 87, 80, 62,
    18, 22, 37, 56, 68,109,103, 77,
    24, 35, 55, 64, 81,104,113, 92,
    49, 64, 78, 87,103,121,120,101,
    72, 92, 95, 98,112,100,103, 99};

__constant__ float cCHR[64] = {
    17, 18, 24, 47, 99, 99, 99, 99,
    18, 21, 26, 66, 99, 99, 99, 99,
    24, 26, 56, 99, 99, 99, 99, 99,
    47, 66, 99, 99, 99, 99, 99, 99,
    99, 99, 99, 99, 99, 99, 99, 99,
    99, 99, 99, 99, 99, 99, 99, 99,
    99, 99, 99, 99, 99, 99, 99, 99,
    99, 99, 99, 99, 99, 99, 99, 99};

__device__ float gD[64];   // DCT-II matrix, row k = frequency
__device__ float gQY[64];  // luma quant table (quality 95)
__device__ float gQC[64];  // chroma quant table

// numpy SIMD float32 cosine (validated R5/R6: CW constant choice immaterial)
__device__ float npy_cosf(float x) {
    const float invpi    = 0x1.45f306p-1f;
    const float rint_cvt = 0x1.8p23f;
    const float hi       = -0x1.921fb0p+0f;
    const float med      = -0x1.5110b4p-22f;
    const float low      = -0x1.846988p-48f;

    float q = __fadd_rn(__fmaf_rn(x, invpi, rint_cvt), -rint_cvt);
    float r = __fmaf_rn(q, hi, x);
    r = __fmaf_rn(q, med, r);
    r = __fmaf_rn(q, low, r);
    float r2 = __fmul_rn(r, r);

    float pc = __fmaf_rn(0x1.98e616p-16f, r2, -0x1.6c06dcp-10f);
    pc = __fmaf_rn(pc, r2, 0x1.55553cp-5f);
    pc = __fmaf_rn(pc, r2, -0x1.000000p-1f);
    pc = __fmaf_rn(pc, r2, 1.0f);

    float ps = __fmaf_rn(0x1.7d3bbcp-19f, r2, -0x1.a06bbap-13f);
    ps = __fmaf_rn(ps, r2, 0x1.11119ap-7f);
    ps = __fmaf_rn(ps, r2, -0x1.555556p-3f);
    ps = __fmul_rn(ps, r2);
    ps = __fmaf_rn(ps, r, r);

    int qi = (int)q;
    int m = qi & 3;
    float v = (m == 0 || m == 2) ? pc : ps;
    return (m == 1 || m == 2) ? -v : v;
}

__global__ void ela_init_tables() {
    int t = threadIdx.x;
    int i = t >> 3;
    int j = t & 7;
    float t2  = (float)((2 * j + 1) * i);
    float ang = __fdiv_rn(__fmul_rn(t2, 3.14159265358979323846f), 16.0f);
    float c = npy_cosf(ang);
    float s = (i == 0) ? (float)sqrt(0.125) : 0.5f;
    gD[t] = __fmul_rn(c, s);
    float qy = floorf(__fdiv_rn(__fadd_rn(__fmul_rn(cLUM[t], 10.0f), 50.0f), 100.0f));
    float qc = floorf(__fdiv_rn(__fadd_rn(__fmul_rn(cCHR[t], 10.0f), 50.0f), 100.0f));
    gQY[t] = fminf(fmaxf(qy, 1.0f), 255.0f);
    gQC[t] = fminf(fmaxf(qc, 1.0f), 255.0f);
}

__device__ __forceinline__ float clip255(float v) {
    return fminf(fmaxf(v, 0.0f), 255.0f);
}

// K=8 dot, reference-exact: NEON 4-wide mul/fma core + ADJACENT-pairs reduce.
__device__ __forceinline__ float dot8(const float* a, const float* b) {
    float c0 = __fmaf_rn(a[4], b[4], __fmul_rn(a[0], b[0]));
    float c1 = __fmaf_rn(a[5], b[5], __fmul_rn(a[1], b[1]));
    float c2 = __fmaf_rn(a[6], b[6], __fmul_rn(a[2], b[2]));
    float c3 = __fmaf_rn(a[7], b[7], __fmul_rn(a[3], b[3]));
    return __fadd_rn(__fadd_rn(c0, c1), __fadd_rn(c2, c3));
}

__global__ __launch_bounds__(256, 4)
void ela_kernel(const float* __restrict__ in, float* __restrict__ out) {
    __shared__ float sD[8][9];
    __shared__ float sQY[64];
    __shared__ float sQC[64];
    __shared__ float sCb[16][17];
    __shared__ float sCr[16][17];
    __shared__ float sA[6][8][9];   // blocks 0-3: Y quadrants, 4: Cb, 5: Cr
    __shared__ float sB[6][8][9];

    const int tid = threadIdx.x;
    if (tid < 64) {
        sD[tid >> 3][tid & 7] = gD[tid];
        sQY[tid] = gQY[tid];
        sQC[tid] = gQC[tid];
    }

    const int tx = tid & 15;
    const int ty = tid >> 4;
    const unsigned y = blockIdx.y * 16 + ty;
    const unsigned x = blockIdx.x * 16 + tx;
    const unsigned base = (((blockIdx.z * 256u + y) * 256u + x) * 3u);

    // ---- load + u8 quantize + RGB->YCbCr ----
    float r = floorf(clip255(__fmul_rn(in[base + 0], 255.0f)));
    float g = floorf(clip255(__fmul_rn(in[base + 1], 255.0f)));
    float b = floorf(clip255(__fmul_rn(in[base + 2], 255.0f)));

    float Yv = __fadd_rn(__fadd_rn(__fmul_rn(0.299f, r), __fmul_rn(0.587f, g)),
                         __fmul_rn(0.114f, b));
    Yv = clip255(rintf(Yv));
    float Cb = __fadd_rn(__fadd_rn(__fadd_rn(__fmul_rn(-0.168736f, r),
                                             __fmul_rn(-0.331264f, g)),
                                   __fmul_rn(0.5f, b)), 128.0f);
    Cb = clip255(rintf(Cb));
    float Cr = __fadd_rn(__fadd_rn(__fadd_rn(__fmul_rn(0.5f, r),
                                             __fmul_rn(-0.418688f, g)),
                                   __fmul_rn(-0.081312f, b)), 128.0f);
    Cr = clip255(rintf(Cr));

    sA[((ty >> 3) << 1) + (tx >> 3)][ty & 7][tx & 7] = __fadd_rn(Yv, -128.0f);
    sCb[ty][tx] = Cb;
    sCr[ty][tx] = Cr;
    __syncthreads();

    // ---- 2x2 chroma downsample ----
    if (tid < 128) {
        int ch = tid >> 6;
        int e = tid & 63;
        int i = e >> 3, j = e & 7;
        float (*src)[17] = ch ? sCr : sCb;
        float sum = __fadd_rn(__fadd_rn(src[2 * i][2 * j], src[2 * i][2 * j + 1]),
                              __fadd_rn(src[2 * i + 1][2 * j], src[2 * i + 1][2 * j + 1]));
        sA[4 + ch][i][j] = __fadd_rn(rintf(__fmul_rn(sum, 0.25f)), -128.0f);
    }
    __syncthreads();

    float av[8], bv[8];

    // ---- forward stage 1: sB = D @ sA ----
    for (int e = tid; e < 384; e += 256) {
        int blk = e >> 6, rr = (e >> 3) & 7, cc = e & 7;
        #pragma unroll
        for (int j = 0; j < 8; j++) { av[j] = sD[rr][j]; bv[j] = sA[blk][j][cc]; }
        sB[blk][rr][cc] = dot8(av, bv);
    }
    __syncthreads();

    // ---- forward stage 2 + quantize ----
    for (int e = tid; e < 384; e += 256) {
        int blk = e >> 6, rr = (e >> 3) & 7, cc = e & 7;
        #pragma unroll
        for (int k = 0; k < 8; k++) { av[k] = sB[blk][rr][k]; bv[k] = sD[cc][k]; }
        float acc = dot8(av, bv);
        float q = (blk < 4 ? sQY : sQC)[rr * 8 + cc];
        sA[blk][rr][cc] = __fmul_rn(rintf(__fdiv_rn(acc, q)), q);
    }
    __syncthreads();

    // ---- inverse stage 1: sB = D^T @ sA ----
    for (int e = tid; e < 384; e += 256) {
        int blk = e >> 6, rr = (e >> 3) & 7, cc = e & 7;
        #pragma unroll
        for (int j = 0; j < 8; j++) { av[j] = sD[j][rr]; bv[j] = sA[blk][j][cc]; }
        sB[blk][rr][cc] = dot8(av, bv);
    }
    __syncthreads();

    // ---- inverse stage 2 + reconstruct ----
    for (int e = tid; e < 384; e += 256) {
        int blk = e >> 6, rr = (e >> 3) & 7, cc = e & 7;
        #pragma unroll
        for (int k = 0; k < 8; k++) { av[k] = sB[blk][rr][k]; bv[k] = sD[k][cc]; }
        float acc = dot8(av, bv);
        sA[blk][rr][cc] = clip255(rintf(__fadd_rn(acc, 128.0f)));
    }
    __syncthreads();

    // ---- YCbCr->RGB, decode, ELA ----
    float Yd = sA[((ty >> 3) << 1) + (tx >> 3)][ty & 7][tx & 7];
    float Cbd = __fadd_rn(sA[4][ty >> 1][tx >> 1], -128.0f);
    float Crd = __fadd_rn(sA[5][ty >> 1][tx >> 1], -128.0f);

    float Rd = __fadd_rn(Yd, __fmul_rn(1.402f, Crd));
    float Gd = __fadd_rn(__fadd_rn(Yd, -__fmul_rn(0.344136f, Cbd)),
                         -__fmul_rn(0.714136f, Crd));
    float Bd = __fadd_rn(Yd, __fmul_rn(1.772f, Cbd));

    float decR = clip255(rintf(Rd));
    float decG = clip255(rintf(Gd));
    float decB = clip255(rintf(Bd));

    out[base + 0] = __fdiv_rn(fabsf(__fadd_rn(r, -decR)), 255.0f);
    out[base + 1] = __fdiv_rn(fabsf(__fadd_rn(g, -decG)), 255.0f);
    out[base + 2] = __fdiv_rn(fabsf(__fadd_rn(b, -decB)), 255.0f);
}

extern "C" void kernel_launch(void* const* d_in, const int* in_sizes, int n_in,
                              void* d_out, int out_size) {
    const float* in = (const float*)d_in[0];
    float* out = (float*)d_out;
    int B = in_sizes[0] / (256 * 256 * 3);

    ela_init_tables<<<1, 64>>>();
    dim3 grid(16, 16, B);
    ela_kernel<<<grid, 256>>>(in, out);
}

// round 12
// speedup vs baseline: 1.1236x; 1.1236x over previous
#include <cuda_runtime.h>
#include <math.h>

// ---------------------------------------------------------------------------
// ELA (JPEG quality-95 roundtrip error) fully fused per 16x16 tile.
// R12: vectorized-LDS DCT. Every stage reads both dot operands as contiguous
// rows (2x LDS.128 each) by keeping transposed/row-major copies per stage:
//   F1: out=D@B        av=D row      bv=B^T row      -> M1 row-major
//   F2: coef=M1@D^T    av=M1 row     bv=D row        -> coef^T
//   I1: out=D^T@coef   av=D^T row    bv=coef^T row   -> M2 row-major
//   I2: rec=M2@D       av=M2 row     bv=D^T row      -> rec row-major
// dot8 bit-exact: c_i = fma(a[i+4],b[i+4], a[i]*b[i]); (c0+c1)+(c2+c3)
// ---------------------------------------------------------------------------

__constant__ float cLUM[64] = {
    16, 11, 10, 16, 24, 40, 51, 61,
    12, 12, 14, 19, 26, 58, 60, 55,
    14, 13, 16, 24, 40, 57, 69, 56,
    14, 17, 22, 29, 51, 87, 80, 62,
    18, 22, 37, 56, 68,109,103, 77,
    24, 35, 55, 64, 81,104,113, 92,
    49, 64, 78, 87,103,121,120,101,
    72, 92, 95, 98,112,100,103, 99};

__constant__ float cCHR[64] = {
    17, 18, 24, 47, 99, 99, 99, 99,
    18, 21, 26, 66, 99, 99, 99, 99,
    24, 26, 56, 99, 99, 99, 99, 99,
    47, 66, 99, 99, 99, 99, 99, 99,
    99, 99, 99, 99, 99, 99, 99, 99,
    99, 99, 99, 99, 99, 99, 99, 99,
    99, 99, 99, 99, 99, 99, 99, 99,
    99, 99, 99, 99, 99, 99, 99, 99};

__device__ float gD[64];
__device__ float gQY[64];
__device__ float gQC[64];

__device__ float npy_cosf(float x) {
    const float invpi    = 0x1.45f306p-1f;
    const float rint_cvt = 0x1.8p23f;
    const float hi       = -0x1.921fb0p+0f;
    const float med      = -0x1.5110b4p-22f;
    const float low      = -0x1.846988p-48f;

    float q = __fadd_rn(__fmaf_rn(x, invpi, rint_cvt), -rint_cvt);
    float r = __fmaf_rn(q, hi, x);
    r = __fmaf_rn(q, med, r);
    r = __fmaf_rn(q, low, r);
    float r2 = __fmul_rn(r, r);

    float pc = __fmaf_rn(0x1.98e616p-16f, r2, -0x1.6c06dcp-10f);
    pc = __fmaf_rn(pc, r2, 0x1.55553cp-5f);
    pc = __fmaf_rn(pc, r2, -0x1.000000p-1f);
    pc = __fmaf_rn(pc, r2, 1.0f);

    float ps = __fmaf_rn(0x1.7d3bbcp-19f, r2, -0x1.a06bbap-13f);
    ps = __fmaf_rn(ps, r2, 0x1.11119ap-7f);
    ps = __fmaf_rn(ps, r2, -0x1.555556p-3f);
    ps = __fmul_rn(ps, r2);
    ps = __fmaf_rn(ps, r, r);

    int qi = (int)q;
    int m = qi & 3;
    float v = (m == 0 || m == 2) ? pc : ps;
    return (m == 1 || m == 2) ? -v : v;
}

__global__ void ela_init_tables() {
    int t = threadIdx.x;
    int i = t >> 3;
    int j = t & 7;
    float t2  = (float)((2 * j + 1) * i);
    float ang = __fdiv_rn(__fmul_rn(t2, 3.14159265358979323846f), 16.0f);
    float c = npy_cosf(ang);
    float s = (i == 0) ? (float)sqrt(0.125) : 0.5f;
    gD[t] = __fmul_rn(c, s);
    float qy = floorf(__fdiv_rn(__fadd_rn(__fmul_rn(cLUM[t], 10.0f), 50.0f), 100.0f));
    float qc = floorf(__fdiv_rn(__fadd_rn(__fmul_rn(cCHR[t], 10.0f), 50.0f), 100.0f));
    gQY[t] = fminf(fmaxf(qy, 1.0f), 255.0f);
    gQC[t] = fminf(fmaxf(qc, 1.0f), 255.0f);
}

__device__ __forceinline__ float clip255(float v) {
    return fminf(fmaxf(v, 0.0f), 255.0f);
}

// Reference-exact K=8 dot on float4 halves.
__device__ __forceinline__ float dot8v(float4 a0, float4 a1, float4 b0, float4 b1) {
    float c0 = __fmaf_rn(a1.x, b1.x, __fmul_rn(a0.x, b0.x));
    float c1 = __fmaf_rn(a1.y, b1.y, __fmul_rn(a0.y, b0.y));
    float c2 = __fmaf_rn(a1.z, b1.z, __fmul_rn(a0.z, b0.z));
    float c3 = __fmaf_rn(a1.w, b1.w, __fmul_rn(a0.w, b0.w));
    return __fadd_rn(__fadd_rn(c0, c1), __fadd_rn(c2, c3));
}

__global__ __launch_bounds__(256)
void ela_kernel(const float* __restrict__ in, float* __restrict__ out) {
    __shared__ __align__(16) float sD[8][12];   // D rows
    __shared__ __align__(16) float sDT[8][12];  // D^T rows (= D columns)
    __shared__ float sQY[64];
    __shared__ float sQC[64];
    __shared__ float sCb[16][17];
    __shared__ float sCr[16][17];
    __shared__ __align__(16) float bufA[6][8][12];  // B^T -> coef^T -> rec
    __shared__ __align__(16) float bufB[6][8][12];  // M1 -> M2

    const int tid = threadIdx.x;
    if (tid < 64) {
        int rI = tid >> 3, cI = tid & 7;
        float d = gD[tid];
        sD[rI][cI] = d;
        sDT[cI][rI] = d;
        sQY[tid] = gQY[tid];
        sQC[tid] = gQC[tid];
    }

    const int tx = tid & 15;
    const int ty = tid >> 4;
    const unsigned y = blockIdx.y * 16 + ty;
    const unsigned x = blockIdx.x * 16 + tx;
    const unsigned base = (((blockIdx.z * 256u + y) * 256u + x) * 3u);
    const int yblk = ((ty >> 3) << 1) + (tx >> 3);

    // ---- load + u8 quantize + RGB->YCbCr (rgb kept in regs for ELA) ----
    float r = floorf(clip255(__fmul_rn(in[base + 0], 255.0f)));
    float g = floorf(clip255(__fmul_rn(in[base + 1], 255.0f)));
    float b = floorf(clip255(__fmul_rn(in[base + 2], 255.0f)));

    float Yv = __fadd_rn(__fadd_rn(__fmul_rn(0.299f, r), __fmul_rn(0.587f, g)),
                         __fmul_rn(0.114f, b));
    Yv = clip255(rintf(Yv));
    float Cb = __fadd_rn(__fadd_rn(__fadd_rn(__fmul_rn(-0.168736f, r),
                                             __fmul_rn(-0.331264f, g)),
                                   __fmul_rn(0.5f, b)), 128.0f);
    Cb = clip255(rintf(Cb));
    float Cr = __fadd_rn(__fadd_rn(__fadd_rn(__fmul_rn(0.5f, r),
                                             __fmul_rn(-0.418688f, g)),
                                   __fmul_rn(-0.081312f, b)), 128.0f);
    Cr = clip255(rintf(Cr));

    // Y stored TRANSPOSED: bufA[blk][x][y]
    bufA[yblk][tx & 7][ty & 7] = __fadd_rn(Yv, -128.0f);
    sCb[ty][tx] = Cb;
    sCr[ty][tx] = Cr;
    __syncthreads();

    // ---- 2x2 chroma downsample -> transposed chroma blocks bufA[4+ch][x][y] ----
    if (tid < 128) {
        int ch = tid >> 6;
        int e = tid & 63;
        int i = e >> 3, j = e & 7;
        float (*src)[17] = ch ? sCr : sCb;
        float sum = __fadd_rn(__fadd_rn(src[2 * i][2 * j], src[2 * i][2 * j + 1]),
                              __fadd_rn(src[2 * i + 1][2 * j], src[2 * i + 1][2 * j + 1]));
        bufA[4 + ch][j][i] = __fadd_rn(rintf(__fmul_rn(sum, 0.25f)), -128.0f);
    }
    __syncthreads();

    // DCT work mapping: 192 threads, each owns (blk,rr) half-fixed, 2 columns
    const bool active = tid < 192;
    const int rI  = tid >> 2;          // 0..47
    const int blk = rI >> 3;           // 0..5
    const int rr  = rI & 7;            // row index
    const int cc0 = (tid & 3) << 1;    // 0,2,4,6

    // ---- F1: M1 = D @ B   (av = D row rr, bv = B^T row cc) ----
    if (active) {
        const float4* ap = (const float4*)sD[rr];
        float4 a0 = ap[0], a1 = ap[1];
        const float4* bp0 = (const float4*)bufA[blk][cc0];
        const float4* bp1 = (const float4*)bufA[blk][cc0 + 1];
        float o0 = dot8v(a0, a1, bp0[0], bp0[1]);
        float o1 = dot8v(a0, a1, bp1[0], bp1[1]);
        *(float2*)&bufB[blk][rr][cc0] = make_float2(o0, o1);
    }
    __syncthreads();

    // ---- F2 + quantize: coef = M1 @ D^T, stored transposed (coef^T) ----
    if (active) {
        const float4* ap = (const float4*)bufB[blk][rr];
        float4 a0 = ap[0], a1 = ap[1];
        const float* Q = (blk < 4) ? sQY : sQC;
        #pragma unroll
        for (int u = 0; u < 2; u++) {
            int c = cc0 + u;
            const float4* bp = (const float4*)sD[c];
            float acc = dot8v(a0, a1, bp[0], bp[1]);
            float q = Q[rr * 8 + c];
            bufA[blk][c][rr] = __fmul_rn(rintf(__fdiv_rn(acc, q)), q);
        }
    }
    __syncthreads();

    // ---- I1: M2 = D^T @ coef  (av = D^T row rr, bv = coef^T row cc) ----
    if (active) {
        const float4* ap = (const float4*)sDT[rr];
        float4 a0 = ap[0], a1 = ap[1];
        const float4* bp0 = (const float4*)bufA[blk][cc0];
        const float4* bp1 = (const float4*)bufA[blk][cc0 + 1];
        float o0 = dot8v(a0, a1, bp0[0], bp0[1]);
        float o1 = dot8v(a0, a1, bp1[0], bp1[1]);
        *(float2*)&bufB[blk][rr][cc0] = make_float2(o0, o1);
    }
    __syncthreads();

    // ---- I2 + reconstruct: rec = M2 @ D (av = M2 row, bv = D^T row cc) ----
    if (active) {
        const float4* ap = (const float4*)bufB[blk][rr];
        float4 a0 = ap[0], a1 = ap[1];
        float o[2];
        #pragma unroll
        for (int u = 0; u < 2; u++) {
            int c = cc0 + u;
            const float4* bp = (const float4*)sDT[c];
            float acc = dot8v(a0, a1, bp[0], bp[1]);
            o[u] = clip255(rintf(__fadd_rn(acc, 128.0f)));
        }
        *(float2*)&bufA[blk][rr][cc0] = make_float2(o[0], o[1]);  // rec[y][x]
    }
    __syncthreads();

    // ---- YCbCr->RGB, decode, ELA ----
    float Yd  = bufA[yblk][ty & 7][tx & 7];
    float Cbd = __fadd_rn(bufA[4][ty >> 1][tx >> 1], -128.0f);
    float Crd = __fadd_rn(bufA[5][ty >> 1][tx >> 1], -128.0f);

    float Rd = __fadd_rn(Yd, __fmul_rn(1.402f, Crd));
    float Gd = __fadd_rn(__fadd_rn(Yd, -__fmul_rn(0.344136f, Cbd)),
                         -__fmul_rn(0.714136f, Crd));
    float Bd = __fadd_rn(Yd, __fmul_rn(1.772f, Cbd));

    float decR = clip255(rintf(Rd));
    float decG = clip255(rintf(Gd));
    float decB = clip255(rintf(Bd));

    out[base + 0] = __fdiv_rn(fabsf(__fadd_rn(r, -decR)), 255.0f);
    out[base + 1] = __fdiv_rn(fabsf(__fadd_rn(g, -decG)), 255.0f);
    out[base + 2] = __fdiv_rn(fabsf(__fadd_rn(b, -decB)), 255.0f);
}

extern "C" void kernel_launch(void* const* d_in, const int* in_sizes, int n_in,
                              void* d_out, int out_size) {
    const float* in = (const float*)d_in[0];
    float* out = (float*)d_out;
    int B = in_sizes[0] / (256 * 256 * 3);

    ela_init_tables<<<1, 64>>>();
    dim3 grid(16, 16, B);
    ela_kernel<<<grid, 256>>>(in, out);
}

// round 13
// speedup vs baseline: 1.4683x; 1.3068x over previous
#include <cuda_runtime.h>
#include <math.h>

// ---------------------------------------------------------------------------
// ELA (JPEG quality-95 roundtrip error), fused per 16x16 tile.
// R13: 4 tiles per CTA; F1+F2 and I1+I2 register-fused (M1/M2 never hit smem);
// every DCT LDS is a <=1-wavefront broadcast; coef^T / rec stored in-place.
// dot8 bit-exact: c_i = fma(a[i+4],b[i+4], a[i]*b[i]); (c0+c1)+(c2+c3)
// ---------------------------------------------------------------------------

__constant__ float cLUM[64] = {
    16, 11, 10, 16, 24, 40, 51, 61,
    12, 12, 14, 19, 26, 58, 60, 55,
    14, 13, 16, 24, 40, 57, 69, 56,
    14, 17, 22, 29, 51, 87, 80, 62,
    18, 22, 37, 56, 68,109,103, 77,
    24, 35, 55, 64, 81,104,113, 92,
    49, 64, 78, 87,103,121,120,101,
    72, 92, 95, 98,112,100,103, 99};

__constant__ float cCHR[64] = {
    17, 18, 24, 47, 99, 99, 99, 99,
    18, 21, 26, 66, 99, 99, 99, 99,
    24, 26, 56, 99, 99, 99, 99, 99,
    47, 66, 99, 99, 99, 99, 99, 99,
    99, 99, 99, 99, 99, 99, 99, 99,
    99, 99, 99, 99, 99, 99, 99, 99,
    99, 99, 99, 99, 99, 99, 99, 99,
    99, 99, 99, 99, 99, 99, 99, 99};

__device__ float gD[64];
__device__ float gQY[64];
__device__ float gQC[64];

__device__ float npy_cosf(float x) {
    const float invpi    = 0x1.45f306p-1f;
    const float rint_cvt = 0x1.8p23f;
    const float hi       = -0x1.921fb0p+0f;
    const float med      = -0x1.5110b4p-22f;
    const float low      = -0x1.846988p-48f;

    float q = __fadd_rn(__fmaf_rn(x, invpi, rint_cvt), -rint_cvt);
    float r = __fmaf_rn(q, hi, x);
    r = __fmaf_rn(q, med, r);
    r = __fmaf_rn(q, low, r);
    float r2 = __fmul_rn(r, r);

    float pc = __fmaf_rn(0x1.98e616p-16f, r2, -0x1.6c06dcp-10f);
    pc = __fmaf_rn(pc, r2, 0x1.55553cp-5f);
    pc = __fmaf_rn(pc, r2, -0x1.000000p-1f);
    pc = __fmaf_rn(pc, r2, 1.0f);

    float ps = __fmaf_rn(0x1.7d3bbcp-19f, r2, -0x1.a06bbap-13f);
    ps = __fmaf_rn(ps, r2, 0x1.11119ap-7f);
    ps = __fmaf_rn(ps, r2, -0x1.555556p-3f);
    ps = __fmul_rn(ps, r2);
    ps = __fmaf_rn(ps, r, r);

    int qi = (int)q;
    int m = qi & 3;
    float v = (m == 0 || m == 2) ? pc : ps;
    return (m == 1 || m == 2) ? -v : v;
}

__global__ void ela_init_tables() {
    int t = threadIdx.x;
    int i = t >> 3;
    int j = t & 7;
    float t2  = (float)((2 * j + 1) * i);
    float ang = __fdiv_rn(__fmul_rn(t2, 3.14159265358979323846f), 16.0f);
    float c = npy_cosf(ang);
    float s = (i == 0) ? (float)sqrt(0.125) : 0.5f;
    gD[t] = __fmul_rn(c, s);
    float qy = floorf(__fdiv_rn(__fadd_rn(__fmul_rn(cLUM[t], 10.0f), 50.0f), 100.0f));
    float qc = floorf(__fdiv_rn(__fadd_rn(__fmul_rn(cCHR[t], 10.0f), 50.0f), 100.0f));
    gQY[t] = fminf(fmaxf(qy, 1.0f), 255.0f);
    gQC[t] = fminf(fmaxf(qc, 1.0f), 255.0f);
}

__device__ __forceinline__ float clip255(float v) {
    return fminf(fmaxf(v, 0.0f), 255.0f);
}

// Reference-exact K=8 dot on float4 halves (operand-commutative, bit-safe).
__device__ __forceinline__ float dot8v(float4 a0, float4 a1, float4 b0, float4 b1) {
    float c0 = __fmaf_rn(a1.x, b1.x, __fmul_rn(a0.x, b0.x));
    float c1 = __fmaf_rn(a1.y, b1.y, __fmul_rn(a0.y, b0.y));
    float c2 = __fmaf_rn(a1.z, b1.z, __fmul_rn(a0.z, b0.z));
    float c3 = __fmaf_rn(a1.w, b1.w, __fmul_rn(a0.w, b0.w));
    return __fadd_rn(__fadd_rn(c0, c1), __fadd_rn(c2, c3));
}

#define NT 4   // tiles per CTA

__global__ __launch_bounds__(256)
void ela_kernel(const float* __restrict__ in, float* __restrict__ out) {
    __shared__ __align__(16) float sD[8][12];
    __shared__ __align__(16) float sDT[8][12];
    __shared__ float sQY[64];
    __shared__ float sQC[64];
    __shared__ float sCb[NT][16][17];
    __shared__ float sCr[NT][16][17];
    __shared__ __align__(16) float bufA[NT][6][8][12]; // B^T -> coef^T -> rec

    const int tid = threadIdx.x;
    if (tid < 64) {
        int rI = tid >> 3, cI = tid & 7;
        float d = gD[tid];
        sD[rI][cI] = d;
        sDT[cI][rI] = d;
        sQY[tid] = gQY[tid];
        sQC[tid] = gQC[tid];
    }

    const int tx = tid & 15;
    const int ty = tid >> 4;
    const int yblk = ((ty >> 3) << 1) + (tx >> 3);
    const unsigned gy = blockIdx.y * 16 + ty;
    const unsigned rowbase = ((blockIdx.z * 256u + gy) * 256u + blockIdx.x * 64u + tx) * 3u;

    // ---- pixel phase: load, u8-quantize, RGB->YCbCr, stage Y^T + chroma ----
    float rv[NT], gv[NT], bv[NT];
    #pragma unroll
    for (int t = 0; t < NT; t++) {
        unsigned base = rowbase + t * 48u;     // 16 px * 3 ch
        float r = floorf(clip255(__fmul_rn(in[base + 0], 255.0f)));
        float g = floorf(clip255(__fmul_rn(in[base + 1], 255.0f)));
        float b = floorf(clip255(__fmul_rn(in[base + 2], 255.0f)));
        rv[t] = r; gv[t] = g; bv[t] = b;

        float Yv = __fadd_rn(__fadd_rn(__fmul_rn(0.299f, r), __fmul_rn(0.587f, g)),
                             __fmul_rn(0.114f, b));
        Yv = clip255(rintf(Yv));
        float Cb = __fadd_rn(__fadd_rn(__fadd_rn(__fmul_rn(-0.168736f, r),
                                                 __fmul_rn(-0.331264f, g)),
                                       __fmul_rn(0.5f, b)), 128.0f);
        Cb = clip255(rintf(Cb));
        float Cr = __fadd_rn(__fadd_rn(__fadd_rn(__fmul_rn(0.5f, r),
                                                 __fmul_rn(-0.418688f, g)),
                                       __fmul_rn(-0.081312f, b)), 128.0f);
        Cr = clip255(rintf(Cr));

        bufA[t][yblk][tx & 7][ty & 7] = __fadd_rn(Yv, -128.0f);  // Y transposed
        sCb[t][ty][tx] = Cb;
        sCr[t][ty][tx] = Cr;
    }
    __syncthreads();

    // ---- 2x2 chroma downsample -> transposed chroma blocks ----
    #pragma unroll
    for (int it = 0; it < 2; it++) {
        int idx = tid + it * 256;              // 0..511 = NT*128
        int t = idx >> 7;
        int ch = (idx >> 6) & 1;
        int e = idx & 63;
        int i = e >> 3, j = e & 7;
        float (*src)[17] = ch ? sCr[t] : sCb[t];
        float sum = __fadd_rn(__fadd_rn(src[2 * i][2 * j], src[2 * i][2 * j + 1]),
                              __fadd_rn(src[2 * i + 1][2 * j], src[2 * i + 1][2 * j + 1]));
        bufA[t][4 + ch][j][i] = __fadd_rn(rintf(__fmul_rn(sum, 0.25f)), -128.0f);
    }
    __syncthreads();

    // ---- DCT phase: 48 threads per tile, thread owns (tile, blk, rr) ----
    const bool active = tid < 48 * NT;
    const int dt  = tid / 48;          // tile
    const int loc = tid - dt * 48;
    const int dblk = loc >> 3;
    const int drr  = loc & 7;
    float4* blkrow = (float4*)bufA[dt][dblk][0];   // 3 float4 per row

    float m[8];

    // ---- stage A: M1 = D @ B (regs), then coef = M1 @ D^T -> coef^T in-place
    if (active) {
        const float4* ap = (const float4*)sD[drr];
        float4 a0 = ap[0], a1 = ap[1];
        #pragma unroll
        for (int c = 0; c < 8; c++) {           // bv = B^T row c (8-way bcast)
            float4 b0 = blkrow[c * 3], b1 = blkrow[c * 3 + 1];
            m[c] = dot8v(a0, a1, b0, b1);
        }
    }
    __syncthreads();                             // all B^T reads complete
    if (active) {
        float4 m0 = make_float4(m[0], m[1], m[2], m[3]);
        float4 m1 = make_float4(m[4], m[5], m[6], m[7]);
        const float* Q = (dblk < 4) ? sQY : sQC;
        #pragma unroll
        for (int c = 0; c < 8; c++) {           // bv = D row c (warp bcast)
            const float4* dp = (const float4*)sD[c];
            float acc = dot8v(m0, m1, dp[0], dp[1]);
            float q = Q[drr * 8 + c];
            bufA[dt][dblk][c][drr] = __fmul_rn(rintf(__fdiv_rn(acc, q)), q);
        }
    }
    __syncthreads();

    // ---- stage B: M2 = D^T @ coef (regs), then rec = M2 @ D -> rec rows
    if (active) {
        const float4* ap = (const float4*)sDT[drr];
        float4 a0 = ap[0], a1 = ap[1];
        #pragma unroll
        for (int c = 0; c < 8; c++) {           // bv = coef^T row c (8-way bcast)
            float4 b0 = blkrow[c * 3], b1 = blkrow[c * 3 + 1];
            m[c] = dot8v(a0, a1, b0, b1);
        }
    }
    __syncthreads();                             // all coef^T reads complete
    if (active) {
        float4 m0 = make_float4(m[0], m[1], m[2], m[3]);
        float4 m1 = make_float4(m[4], m[5], m[6], m[7]);
        float o[8];
        #pragma unroll
        for (int c = 0; c < 8; c++) {           // bv = D^T row c (warp bcast)
            const float4* dp = (const float4*)sDT[c];
            float acc = dot8v(m0, m1, dp[0], dp[1]);
            o[c] = clip255(rintf(__fadd_rn(acc, 128.0f)));
        }
        float4* orow = (float4*)bufA[dt][dblk][drr];      // rec row-major
        orow[0] = make_float4(o[0], o[1], o[2], o[3]);
        orow[1] = make_float4(o[4], o[5], o[6], o[7]);
    }
    __syncthreads();

    // ---- final: YCbCr->RGB decode, ELA, store ----
    #pragma unroll
    for (int t = 0; t < NT; t++) {
        float Yd  = bufA[t][yblk][ty & 7][tx & 7];
        float Cbd = __fadd_rn(bufA[t][4][ty >> 1][tx >> 1], -128.0f);
        float Crd = __fadd_rn(bufA[t][5][ty >> 1][tx >> 1], -128.0f);

        float Rd = __fadd_rn(Yd, __fmul_rn(1.402f, Crd));
        float Gd = __fadd_rn(__fadd_rn(Yd, -__fmul_rn(0.344136f, Cbd)),
                             -__fmul_rn(0.714136f, Crd));
        float Bd = __fadd_rn(Yd, __fmul_rn(1.772f, Cbd));

        float decR = clip255(rintf(Rd));
        float decG = clip255(rintf(Gd));
        float decB = clip255(rintf(Bd));

        unsigned base = rowbase + t * 48u;
        out[base + 0] = __fdiv_rn(fabsf(__fadd_rn(rv[t], -decR)), 255.0f);
        out[base + 1] = __fdiv_rn(fabsf(__fadd_rn(gv[t], -decG)), 255.0f);
        out[base + 2] = __fdiv_rn(fabsf(__fadd_rn(bv[t], -decB)), 255.0f);
    }
}

extern "C" void kernel_launch(void* const* d_in, const int* in_sizes, int n_in,
                              void* d_out, int out_size) {
    const float* in = (const float*)d_in[0];
    float* out = (float*)d_out;
    int B = in_sizes[0] / (256 * 256 * 3);

    ela_init_tables<<<1, 64>>>();
    dim3 grid(4, 16, B);
    ela_kernel<<<grid, 256>>>(in, out);
}

// round 14
// speedup vs baseline: 1.5123x; 1.0299x over previous
#include <cuda_runtime.h>
#include <math.h>

// ---------------------------------------------------------------------------
// ELA (JPEG quality-95 roundtrip error), fused per 16x16 tile.
// R14: bank-conflict-free DCT (block stride 104), shuffle-based chroma
// downsample (no sCb/sCr staging), 64-thread-per-tile DCT groups, warp-level
// syncs inside the DCT. dot8 bit-exact vs reference:
//   c_i = fma(a[i+4],b[i+4], a[i]*b[i]); (c0+c1)+(c2+c3)
// ---------------------------------------------------------------------------

__constant__ float cLUM[64] = {
    16, 11, 10, 16, 24, 40, 51, 61,
    12, 12, 14, 19, 26, 58, 60, 55,
    14, 13, 16, 24, 40, 57, 69, 56,
    14, 17, 22, 29, 51, 87, 80, 62,
    18, 22, 37, 56, 68,109,103, 77,
    24, 35, 55, 64, 81,104,113, 92,
    49, 64, 78, 87,103,121,120,101,
    72, 92, 95, 98,112,100,103, 99};

__constant__ float cCHR[64] = {
    17, 18, 24, 47, 99, 99, 99, 99,
    18, 21, 26, 66, 99, 99, 99, 99,
    24, 26, 56, 99, 99, 99, 99, 99,
    47, 66, 99, 99, 99, 99, 99, 99,
    99, 99, 99, 99, 99, 99, 99, 99,
    99, 99, 99, 99, 99, 99, 99, 99,
    99, 99, 99, 99, 99, 99, 99, 99,
    99, 99, 99, 99, 99, 99, 99, 99};

__device__ float gD[64];
__device__ float gQY[64];
__device__ float gQC[64];

__device__ float npy_cosf(float x) {
    const float invpi    = 0x1.45f306p-1f;
    const float rint_cvt = 0x1.8p23f;
    const float hi       = -0x1.921fb0p+0f;
    const float med      = -0x1.5110b4p-22f;
    const float low      = -0x1.846988p-48f;

    float q = __fadd_rn(__fmaf_rn(x, invpi, rint_cvt), -rint_cvt);
    float r = __fmaf_rn(q, hi, x);
    r = __fmaf_rn(q, med, r);
    r = __fmaf_rn(q, low, r);
    float r2 = __fmul_rn(r, r);

    float pc = __fmaf_rn(0x1.98e616p-16f, r2, -0x1.6c06dcp-10f);
    pc = __fmaf_rn(pc, r2, 0x1.55553cp-5f);
    pc = __fmaf_rn(pc, r2, -0x1.000000p-1f);
    pc = __fmaf_rn(pc, r2, 1.0f);

    float ps = __fmaf_rn(0x1.7d3bbcp-19f, r2, -0x1.a06bbap-13f);
    ps = __fmaf_rn(ps, r2, 0x1.11119ap-7f);
    ps = __fmaf_rn(ps, r2, -0x1.555556p-3f);
    ps = __fmul_rn(ps, r2);
    ps = __fmaf_rn(ps, r, r);

    int qi = (int)q;
    int m = qi & 3;
    float v = (m == 0 || m == 2) ? pc : ps;
    return (m == 1 || m == 2) ? -v : v;
}

__global__ void ela_init_tables() {
    int t = threadIdx.x;
    int i = t >> 3;
    int j = t & 7;
    float t2  = (float)((2 * j + 1) * i);
    float ang = __fdiv_rn(__fmul_rn(t2, 3.14159265358979323846f), 16.0f);
    float c = npy_cosf(ang);
    float s = (i == 0) ? (float)sqrt(0.125) : 0.5f;
    gD[t] = __fmul_rn(c, s);
    float qy = floorf(__fdiv_rn(__fadd_rn(__fmul_rn(cLUM[t], 10.0f), 50.0f), 100.0f));
    float qc = floorf(__fdiv_rn(__fadd_rn(__fmul_rn(cCHR[t], 10.0f), 50.0f), 100.0f));
    gQY[t] = fminf(fmaxf(qy, 1.0f), 255.0f);
    gQC[t] = fminf(fmaxf(qc, 1.0f), 255.0f);
}

__device__ __forceinline__ float clip255(float v) {
    return fminf(fmaxf(v, 0.0f), 255.0f);
}

// Reference-exact K=8 dot on float4 halves.
__device__ __forceinline__ float dot8v(float4 a0, float4 a1, float4 b0, float4 b1) {
    float c0 = __fmaf_rn(a1.x, b1.x, __fmul_rn(a0.x, b0.x));
    float c1 = __fmaf_rn(a1.y, b1.y, __fmul_rn(a0.y, b0.y));
    float c2 = __fmaf_rn(a1.z, b1.z, __fmul_rn(a0.z, b0.z));
    float c3 = __fmaf_rn(a1.w, b1.w, __fmul_rn(a0.w, b0.w));
    return __fadd_rn(__fadd_rn(c0, c1), __fadd_rn(c2, c3));
}

#define NT 4          // tiles per CTA
#define BSTR 104      // block stride in floats (8 rows x 12 + 8 pad) - bank skew
#define TSTR (6 * BSTR)

__global__ __launch_bounds__(256)
void ela_kernel(const float* __restrict__ in, float* __restrict__ out) {
    __shared__ __align__(16) float sD[8][12];
    __shared__ __align__(16) float sDT[8][12];
    __shared__ float sQY[64];
    __shared__ float sQC[64];
    __shared__ __align__(16) float buf[NT * TSTR];  // B^T -> coef^T -> rec

    const int tid = threadIdx.x;
    if (tid < 64) {
        int rI = tid >> 3, cI = tid & 7;
        float d = gD[tid];
        sD[rI][cI] = d;
        sDT[cI][rI] = d;
        sQY[tid] = gQY[tid];
        sQC[tid] = gQC[tid];
    }

    const int tx = tid & 15;
    const int ty = tid >> 4;
    const int yblk = ((ty >> 3) << 1) + (tx >> 3);
    const unsigned gy = blockIdx.y * 16 + ty;
    const unsigned rowbase = ((blockIdx.z * 256u + gy) * 256u + blockIdx.x * 64u + tx) * 3u;
    const bool cwrite = ((tx & 1) | (ty & 1)) == 0;   // even-even: chroma writer

    // ---- pixel phase: load, u8-quantize, RGB->YCbCr, stage Y^T + chroma ----
    float rv[NT], gv[NT], bv[NT];
    #pragma unroll
    for (int t = 0; t < NT; t++) {
        unsigned base = rowbase + t * 48u;
        float r = floorf(clip255(__fmul_rn(in[base + 0], 255.0f)));
        float g = floorf(clip255(__fmul_rn(in[base + 1], 255.0f)));
        float b = floorf(clip255(__fmul_rn(in[base + 2], 255.0f)));
        rv[t] = r; gv[t] = g; bv[t] = b;

        float Yv = __fadd_rn(__fadd_rn(__fmul_rn(0.299f, r), __fmul_rn(0.587f, g)),
                             __fmul_rn(0.114f, b));
        Yv = clip255(rintf(Yv));
        float Cb = __fadd_rn(__fadd_rn(__fadd_rn(__fmul_rn(-0.168736f, r),
                                                 __fmul_rn(-0.331264f, g)),
                                       __fmul_rn(0.5f, b)), 128.0f);
        Cb = clip255(rintf(Cb));
        float Cr = __fadd_rn(__fadd_rn(__fadd_rn(__fmul_rn(0.5f, r),
                                                 __fmul_rn(-0.418688f, g)),
                                       __fmul_rn(-0.081312f, b)), 128.0f);
        Cr = clip255(rintf(Cr));

        // Y stored transposed: buf[... yblk][x][y]
        buf[t * TSTR + yblk * BSTR + (tx & 7) * 12 + (ty & 7)] = __fadd_rn(Yv, -128.0f);

        // 2x2 downsample via warp shuffles (exact integer sums)
        float s1b = __fadd_rn(Cb, __shfl_xor_sync(0xffffffffu, Cb, 1));
        float s1r = __fadd_rn(Cr, __shfl_xor_sync(0xffffffffu, Cr, 1));
        float s2b = __fadd_rn(s1b, __shfl_xor_sync(0xffffffffu, s1b, 16));
        float s2r = __fadd_rn(s1r, __shfl_xor_sync(0xffffffffu, s1r, 16));
        if (cwrite) {
            int j = tx >> 1, i = ty >> 1;     // chroma stored transposed [j][i]
            buf[t * TSTR + 4 * BSTR + j * 12 + i] =
                __fadd_rn(rintf(__fmul_rn(s2b, 0.25f)), -128.0f);
            buf[t * TSTR + 5 * BSTR + j * 12 + i] =
                __fadd_rn(rintf(__fmul_rn(s2r, 0.25f)), -128.0f);
        }
    }
    __syncthreads();

    // ---- DCT phase: 64-thread groups per tile, thread owns (blk, rr) ----
    const int dt  = tid >> 6;
    const int loc = tid & 63;
    const bool active = loc < 48;
    const int dblk = loc >> 3;
    const int drr  = loc & 7;
    float* blkbase = &buf[dt * TSTR + dblk * BSTR];

    float m[8];

    // stage A-1: M1 row = D[drr] . B^T rows (B^T broadcast, conflict-free)
    if (active) {
        float4 a0 = *(const float4*)&sD[drr][0];
        float4 a1 = *(const float4*)&sD[drr][4];
        #pragma unroll
        for (int c = 0; c < 8; c++) {
            float4 b0 = *(const float4*)&blkbase[c * 12];
            float4 b1 = *(const float4*)&blkbase[c * 12 + 4];
            m[c] = dot8v(a0, a1, b0, b1);
        }
    }
    __syncwarp();
    // stage A-2: coef row = M1 row . D rows; quantize; store coef^T in-place
    if (active) {
        float4 m0 = make_float4(m[0], m[1], m[2], m[3]);
        float4 m1 = make_float4(m[4], m[5], m[6], m[7]);
        const float* Q = (dblk < 4) ? sQY : sQC;
        #pragma unroll
        for (int c = 0; c < 8; c++) {
            float4 d0 = *(const float4*)&sD[c][0];
            float4 d1 = *(const float4*)&sD[c][4];
            float acc = dot8v(m0, m1, d0, d1);
            float q = Q[drr * 8 + c];
            blkbase[c * 12 + drr] = __fmul_rn(rintf(__fdiv_rn(acc, q)), q);
        }
    }
    __syncwarp();
    // stage B-1: M2 row = D^T[drr] . coef^T rows
    if (active) {
        float4 a0 = *(const float4*)&sDT[drr][0];
        float4 a1 = *(const float4*)&sDT[drr][4];
        #pragma unroll
        for (int c = 0; c < 8; c++) {
            float4 b0 = *(const float4*)&blkbase[c * 12];
            float4 b1 = *(const float4*)&blkbase[c * 12 + 4];
            m[c] = dot8v(a0, a1, b0, b1);
        }
    }
    __syncwarp();
    // stage B-2: rec row = M2 row . D^T rows; store row-major (float4 x2)
    if (active) {
        float4 m0 = make_float4(m[0], m[1], m[2], m[3]);
        float4 m1 = make_float4(m[4], m[5], m[6], m[7]);
        float o[8];
        #pragma unroll
        for (int c = 0; c < 8; c++) {
            float4 d0 = *(const float4*)&sDT[c][0];
            float4 d1 = *(const float4*)&sDT[c][4];
            float acc = dot8v(m0, m1, d0, d1);
            o[c] = clip255(rintf(__fadd_rn(acc, 128.0f)));
        }
        float4* orow = (float4*)&blkbase[drr * 12];
        orow[0] = make_float4(o[0], o[1], o[2], o[3]);
        orow[1] = make_float4(o[4], o[5], o[6], o[7]);
    }
    __syncthreads();

    // ---- final: YCbCr->RGB decode, ELA, store ----
    #pragma unroll
    for (int t = 0; t < NT; t++) {
        float Yd  = buf[t * TSTR + yblk * BSTR + (ty & 7) * 12 + (tx & 7)];
        float Cbd = __fadd_rn(buf[t * TSTR + 4 * BSTR + (ty >> 1) * 12 + (tx >> 1)], -128.0f);
        float Crd = __fadd_rn(buf[t * TSTR + 5 * BSTR + (ty >> 1) * 12 + (tx >> 1)], -128.0f);

        float Rd = __fadd_rn(Yd, __fmul_rn(1.402f, Crd));
        float Gd = __fadd_rn(__fadd_rn(Yd, -__fmul_rn(0.344136f, Cbd)),
                             -__fmul_rn(0.714136f, Crd));
        float Bd = __fadd_rn(Yd, __fmul_rn(1.772f, Cbd));

        float decR = clip255(rintf(Rd));
        float decG = clip255(rintf(Gd));
        float decB = clip255(rintf(Bd));

        unsigned base = rowbase + t * 48u;
        out[base + 0] = __fdiv_rn(fabsf(__fadd_rn(rv[t], -decR)), 255.0f);
        out[base + 1] = __fdiv_rn(fabsf(__fadd_rn(gv[t], -decG)), 255.0f);
        out[base + 2] = __fdiv_rn(fabsf(__fadd_rn(bv[t], -decB)), 255.0f);
    }
}

extern "C" void kernel_launch(void* const* d_in, const int* in_sizes, int n_in,
                              void* d_out, int out_size) {
    const float* in = (const float*)d_in[0];
    float* out = (float*)d_out;
    int B = in_sizes[0] / (256 * 256 * 3);

    ela_init_tables<<<1, 64>>>();
    dim3 grid(4, 16, B);
    ela_kernel<<<grid, 256>>>(in, out);
}

// round 15
// speedup vs baseline: 1.6052x; 1.0614x over previous
#include <cuda_runtime.h>
#include <math.h>

// ---------------------------------------------------------------------------
// ELA (JPEG quality-95 roundtrip error), fused per 16x16 tile.
// R15: (a) rgb regs dropped — input re-read in epilogue (L1-resident),
//      (b) |u8-dec|/255 via 256-entry shared LUT (bit-exact, replaces fdiv),
//      (c) occupancy 4->5 CTAs/SM from register savings.
// DCT layout: block stride 104 floats (bank-skewed, conflict-free).
// dot8 bit-exact: c_i = fma(a[i+4],b[i+4], a[i]*b[i]); (c0+c1)+(c2+c3)
// ---------------------------------------------------------------------------

__constant__ float cLUM[64] = {
    16, 11, 10, 16, 24, 40, 51, 61,
    12, 12, 14, 19, 26, 58, 60, 55,
    14, 13, 16, 24, 40, 57, 69, 56,
    14, 17, 22, 29, 51, 87, 80, 62,
    18, 22, 37, 56, 68,109,103, 77,
    24, 35, 55, 64, 81,104,113, 92,
    49, 64, 78, 87,103,121,120,101,
    72, 92, 95, 98,112,100,103, 99};

__constant__ float cCHR[64] = {
    17, 18, 24, 47, 99, 99, 99, 99,
    18, 21, 26, 66, 99, 99, 99, 99,
    24, 26, 56, 99, 99, 99, 99, 99,
    47, 66, 99, 99, 99, 99, 99, 99,
    99, 99, 99, 99, 99, 99, 99, 99,
    99, 99, 99, 99, 99, 99, 99, 99,
    99, 99, 99, 99, 99, 99, 99, 99,
    99, 99, 99, 99, 99, 99, 99, 99};

__device__ float gD[64];
__device__ float gQY[64];
__device__ float gQC[64];

__device__ float npy_cosf(float x) {
    const float invpi    = 0x1.45f306p-1f;
    const float rint_cvt = 0x1.8p23f;
    const float hi       = -0x1.921fb0p+0f;
    const float med      = -0x1.5110b4p-22f;
    const float low      = -0x1.846988p-48f;

    float q = __fadd_rn(__fmaf_rn(x, invpi, rint_cvt), -rint_cvt);
    float r = __fmaf_rn(q, hi, x);
    r = __fmaf_rn(q, med, r);
    r = __fmaf_rn(q, low, r);
    float r2 = __fmul_rn(r, r);

    float pc = __fmaf_rn(0x1.98e616p-16f, r2, -0x1.6c06dcp-10f);
    pc = __fmaf_rn(pc, r2, 0x1.55553cp-5f);
    pc = __fmaf_rn(pc, r2, -0x1.000000p-1f);
    pc = __fmaf_rn(pc, r2, 1.0f);

    float ps = __fmaf_rn(0x1.7d3bbcp-19f, r2, -0x1.a06bbap-13f);
    ps = __fmaf_rn(ps, r2, 0x1.11119ap-7f);
    ps = __fmaf_rn(ps, r2, -0x1.555556p-3f);
    ps = __fmul_rn(ps, r2);
    ps = __fmaf_rn(ps, r, r);

    int qi = (int)q;
    int m = qi & 3;
    float v = (m == 0 || m == 2) ? pc : ps;
    return (m == 1 || m == 2) ? -v : v;
}

__global__ void ela_init_tables() {
    int t = threadIdx.x;
    int i = t >> 3;
    int j = t & 7;
    float t2  = (float)((2 * j + 1) * i);
    float ang = __fdiv_rn(__fmul_rn(t2, 3.14159265358979323846f), 16.0f);
    float c = npy_cosf(ang);
    float s = (i == 0) ? (float)sqrt(0.125) : 0.5f;
    gD[t] = __fmul_rn(c, s);
    float qy = floorf(__fdiv_rn(__fadd_rn(__fmul_rn(cLUM[t], 10.0f), 50.0f), 100.0f));
    float qc = floorf(__fdiv_rn(__fadd_rn(__fmul_rn(cCHR[t], 10.0f), 50.0f), 100.0f));
    gQY[t] = fminf(fmaxf(qy, 1.0f), 255.0f);
    gQC[t] = fminf(fmaxf(qc, 1.0f), 255.0f);
}

__device__ __forceinline__ float clip255(float v) {
    return fminf(fmaxf(v, 0.0f), 255.0f);
}

// Reference-exact K=8 dot on float4 halves.
__device__ __forceinline__ float dot8v(float4 a0, float4 a1, float4 b0, float4 b1) {
    float c0 = __fmaf_rn(a1.x, b1.x, __fmul_rn(a0.x, b0.x));
    float c1 = __fmaf_rn(a1.y, b1.y, __fmul_rn(a0.y, b0.y));
    float c2 = __fmaf_rn(a1.z, b1.z, __fmul_rn(a0.z, b0.z));
    float c3 = __fmaf_rn(a1.w, b1.w, __fmul_rn(a0.w, b0.w));
    return __fadd_rn(__fadd_rn(c0, c1), __fadd_rn(c2, c3));
}

#define NT 4          // tiles per CTA
#define BSTR 104      // block stride in floats - bank skew
#define TSTR (6 * BSTR)

__global__ __launch_bounds__(256, 5)
void ela_kernel(const float* __restrict__ in, float* __restrict__ out) {
    __shared__ __align__(16) float sD[8][12];
    __shared__ __align__(16) float sDT[8][12];
    __shared__ float sQY[64];
    __shared__ float sQC[64];
    __shared__ float sLUT[256];                     // n/255 exact
    __shared__ __align__(16) float buf[NT * TSTR];  // B^T -> coef^T -> rec

    const int tid = threadIdx.x;
    sLUT[tid] = __fdiv_rn((float)tid, 255.0f);
    if (tid < 64) {
        int rI = tid >> 3, cI = tid & 7;
        float d = gD[tid];
        sD[rI][cI] = d;
        sDT[cI][rI] = d;
        sQY[tid] = gQY[tid];
        sQC[tid] = gQC[tid];
    }

    const int tx = tid & 15;
    const int ty = tid >> 4;
    const int yblk = ((ty >> 3) << 1) + (tx >> 3);
    const unsigned gy = blockIdx.y * 16 + ty;
    const unsigned rowbase = ((blockIdx.z * 256u + gy) * 256u + blockIdx.x * 64u + tx) * 3u;
    const bool cwrite = ((tx & 1) | (ty & 1)) == 0;   // even-even: chroma writer

    // ---- pixel phase: load, u8-quantize, RGB->YCbCr, stage Y^T + chroma ----
    #pragma unroll
    for (int t = 0; t < NT; t++) {
        unsigned base = rowbase + t * 48u;
        float r = floorf(clip255(__fmul_rn(in[base + 0], 255.0f)));
        float g = floorf(clip255(__fmul_rn(in[base + 1], 255.0f)));
        float b = floorf(clip255(__fmul_rn(in[base + 2], 255.0f)));

        float Yv = __fadd_rn(__fadd_rn(__fmul_rn(0.299f, r), __fmul_rn(0.587f, g)),
                             __fmul_rn(0.114f, b));
        Yv = clip255(rintf(Yv));
        float Cb = __fadd_rn(__fadd_rn(__fadd_rn(__fmul_rn(-0.168736f, r),
                                                 __fmul_rn(-0.331264f, g)),
                                       __fmul_rn(0.5f, b)), 128.0f);
        Cb = clip255(rintf(Cb));
        float Cr = __fadd_rn(__fadd_rn(__fadd_rn(__fmul_rn(0.5f, r),
                                                 __fmul_rn(-0.418688f, g)),
                                       __fmul_rn(-0.081312f, b)), 128.0f);
        Cr = clip255(rintf(Cr));

        // Y stored transposed: buf[... yblk][x][y]
        buf[t * TSTR + yblk * BSTR + (tx & 7) * 12 + (ty & 7)] = __fadd_rn(Yv, -128.0f);

        // 2x2 downsample via warp shuffles (exact integer sums)
        float s1b = __fadd_rn(Cb, __shfl_xor_sync(0xffffffffu, Cb, 1));
        float s1r = __fadd_rn(Cr, __shfl_xor_sync(0xffffffffu, Cr, 1));
        float s2b = __fadd_rn(s1b, __shfl_xor_sync(0xffffffffu, s1b, 16));
        float s2r = __fadd_rn(s1r, __shfl_xor_sync(0xffffffffu, s1r, 16));
        if (cwrite) {
            int j = tx >> 1, i = ty >> 1;     // chroma stored transposed [j][i]
            buf[t * TSTR + 4 * BSTR + j * 12 + i] =
                __fadd_rn(rintf(__fmul_rn(s2b, 0.25f)), -128.0f);
            buf[t * TSTR + 5 * BSTR + j * 12 + i] =
                __fadd_rn(rintf(__fmul_rn(s2r, 0.25f)), -128.0f);
        }
    }
    __syncthreads();

    // ---- DCT phase: 64-thread groups per tile, thread owns (blk, rr) ----
    const int dt  = tid >> 6;
    const int loc = tid & 63;
    const bool active = loc < 48;
    const int dblk = loc >> 3;
    const int drr  = loc & 7;
    float* blkbase = &buf[dt * TSTR + dblk * BSTR];

    float m[8];

    // stage A-1: M1 row = D[drr] . B^T rows
    if (active) {
        float4 a0 = *(const float4*)&sD[drr][0];
        float4 a1 = *(const float4*)&sD[drr][4];
        #pragma unroll
        for (int c = 0; c < 8; c++) {
            float4 b0 = *(const float4*)&blkbase[c * 12];
            float4 b1 = *(const float4*)&blkbase[c * 12 + 4];
            m[c] = dot8v(a0, a1, b0, b1);
        }
    }
    __syncwarp();
    // stage A-2: coef row = M1 row . D rows; quantize; store coef^T in-place
    if (active) {
        float4 m0 = make_float4(m[0], m[1], m[2], m[3]);
        float4 m1 = make_float4(m[4], m[5], m[6], m[7]);
        const float* Q = (dblk < 4) ? sQY : sQC;
        #pragma unroll
        for (int c = 0; c < 8; c++) {
            float4 d0 = *(const float4*)&sD[c][0];
            float4 d1 = *(const float4*)&sD[c][4];
            float acc = dot8v(m0, m1, d0, d1);
            float q = Q[drr * 8 + c];
            blkbase[c * 12 + drr] = __fmul_rn(rintf(__fdiv_rn(acc, q)), q);
        }
    }
    __syncwarp();
    // stage B-1: M2 row = D^T[drr] . coef^T rows
    if (active) {
        float4 a0 = *(const float4*)&sDT[drr][0];
        float4 a1 = *(const float4*)&sDT[drr][4];
        #pragma unroll
        for (int c = 0; c < 8; c++) {
            float4 b0 = *(const float4*)&blkbase[c * 12];
            float4 b1 = *(const float4*)&blkbase[c * 12 + 4];
            m[c] = dot8v(a0, a1, b0, b1);
        }
    }
    __syncwarp();
    // stage B-2: rec row = M2 row . D^T rows; store row-major
    if (active) {
        float4 m0 = make_float4(m[0], m[1], m[2], m[3]);
        float4 m1 = make_float4(m[4], m[5], m[6], m[7]);
        float o[8];
        #pragma unroll
        for (int c = 0; c < 8; c++) {
            float4 d0 = *(const float4*)&sDT[c][0];
            float4 d1 = *(const float4*)&sDT[c][4];
            float acc = dot8v(m0, m1, d0, d1);
            o[c] = clip255(rintf(__fadd_rn(acc, 128.0f)));
        }
        float4* orow = (float4*)&blkbase[drr * 12];
        orow[0] = make_float4(o[0], o[1], o[2], o[3]);
        orow[1] = make_float4(o[4], o[5], o[6], o[7]);
    }
    __syncthreads();

    // ---- final: re-read input (L1-hit), decode, ELA via LUT, store ----
    #pragma unroll
    for (int t = 0; t < NT; t++) {
        unsigned base = rowbase + t * 48u;
        float r = floorf(clip255(__fmul_rn(in[base + 0], 255.0f)));
        float g = floorf(clip255(__fmul_rn(in[base + 1], 255.0f)));
        float b = floorf(clip255(__fmul_rn(in[base + 2], 255.0f)));

        float Yd  = buf[t * TSTR + yblk * BSTR + (ty & 7) * 12 + (tx & 7)];
        float Cbd = __fadd_rn(buf[t * TSTR + 4 * BSTR + (ty >> 1) * 12 + (tx >> 1)], -128.0f);
        float Crd = __fadd_rn(buf[t * TSTR + 5 * BSTR + (ty >> 1) * 12 + (tx >> 1)], -128.0f);

        float Rd = __fadd_rn(Yd, __fmul_rn(1.402f, Crd));
        float Gd = __fadd_rn(__fadd_rn(Yd, -__fmul_rn(0.344136f, Cbd)),
                             -__fmul_rn(0.714136f, Crd));
        float Bd = __fadd_rn(Yd, __fmul_rn(1.772f, Cbd));

        float decR = clip255(rintf(Rd));
        float decG = clip255(rintf(Gd));
        float decB = clip255(rintf(Bd));

        // |u8 - dec| is an exact integer 0..255 -> LUT gives fdiv-rn-exact n/255
        out[base + 0] = sLUT[__float2int_rn(fabsf(__fadd_rn(r, -decR)))];
        out[base + 1] = sLUT[__float2int_rn(fabsf(__fadd_rn(g, -decG)))];
        out[base + 2] = sLUT[__float2int_rn(fabsf(__fadd_rn(b, -decB)))];
    }
}

extern "C" void kernel_launch(void* const* d_in, const int* in_sizes, int n_in,
                              void* d_out, int out_size) {
    const float* in = (const float*)d_in[0];
    float* out = (float*)d_out;
    int B = in_sizes[0] / (256 * 256 * 3);

    ela_init_tables<<<1, 64>>>();
    dim3 grid(4, 16, B);
    ela_kernel<<<grid, 256>>>(in, out);
}

// round 16
// speedup vs baseline: 1.7793x; 1.1084x over previous
#include <cuda_runtime.h>
#include <math.h>

// ---------------------------------------------------------------------------
// ELA (JPEG quality-95 roundtrip error), fused per 16x16 tile.
// R16: DCT work PACKED into threads 0..191 (48/tile contiguous) so 2 of 8
// warps idle completely instead of 4 warps running half-predicated: -25% of
// DCT issue slots. Blocks stay 8-lane aligned -> warp-local hazards, and the
// stride-104 bank skew keeps every access pattern conflict-free.
// dot8 bit-exact: c_i = fma(a[i+4],b[i+4], a[i]*b[i]); (c0+c1)+(c2+c3)
// ---------------------------------------------------------------------------

__constant__ float cLUM[64] = {
    16, 11, 10, 16, 24, 40, 51, 61,
    12, 12, 14, 19, 26, 58, 60, 55,
    14, 13, 16, 24, 40, 57, 69, 56,
    14, 17, 22, 29, 51, 87, 80, 62,
    18, 22, 37, 56, 68,109,103, 77,
    24, 35, 55, 64, 81,104,113, 92,
    49, 64, 78, 87,103,121,120,101,
    72, 92, 95, 98,112,100,103, 99};

__constant__ float cCHR[64] = {
    17, 18, 24, 47, 99, 99, 99, 99,
    18, 21, 26, 66, 99, 99, 99, 99,
    24, 26, 56, 99, 99, 99, 99, 99,
    47, 66, 99, 99, 99, 99, 99, 99,
    99, 99, 99, 99, 99, 99, 99, 99,
    99, 99, 99, 99, 99, 99, 99, 99,
    99, 99, 99, 99, 99, 99, 99, 99,
    99, 99, 99, 99, 99, 99, 99, 99};

__device__ float gD[64];
__device__ float gQY[64];
__device__ float gQC[64];

__device__ float npy_cosf(float x) {
    const float invpi    = 0x1.45f306p-1f;
    const float rint_cvt = 0x1.8p23f;
    const float hi       = -0x1.921fb0p+0f;
    const float med      = -0x1.5110b4p-22f;
    const float low      = -0x1.846988p-48f;

    float q = __fadd_rn(__fmaf_rn(x, invpi, rint_cvt), -rint_cvt);
    float r = __fmaf_rn(q, hi, x);
    r = __fmaf_rn(q, med, r);
    r = __fmaf_rn(q, low, r);
    float r2 = __fmul_rn(r, r);

    float pc = __fmaf_rn(0x1.98e616p-16f, r2, -0x1.6c06dcp-10f);
    pc = __fmaf_rn(pc, r2, 0x1.55553cp-5f);
    pc = __fmaf_rn(pc, r2, -0x1.000000p-1f);
    pc = __fmaf_rn(pc, r2, 1.0f);

    float ps = __fmaf_rn(0x1.7d3bbcp-19f, r2, -0x1.a06bbap-13f);
    ps = __fmaf_rn(ps, r2, 0x1.11119ap-7f);
    ps = __fmaf_rn(ps, r2, -0x1.555556p-3f);
    ps = __fmul_rn(ps, r2);
    ps = __fmaf_rn(ps, r, r);

    int qi = (int)q;
    int m = qi & 3;
    float v = (m == 0 || m == 2) ? pc : ps;
    return (m == 1 || m == 2) ? -v : v;
}

__global__ void ela_init_tables() {
    int t = threadIdx.x;
    int i = t >> 3;
    int j = t & 7;
    float t2  = (float)((2 * j + 1) * i);
    float ang = __fdiv_rn(__fmul_rn(t2, 3.14159265358979323846f), 16.0f);
    float c = npy_cosf(ang);
    float s = (i == 0) ? (float)sqrt(0.125) : 0.5f;
    gD[t] = __fmul_rn(c, s);
    float qy = floorf(__fdiv_rn(__fadd_rn(__fmul_rn(cLUM[t], 10.0f), 50.0f), 100.0f));
    float qc = floorf(__fdiv_rn(__fadd_rn(__fmul_rn(cCHR[t], 10.0f), 50.0f), 100.0f));
    gQY[t] = fminf(fmaxf(qy, 1.0f), 255.0f);
    gQC[t] = fminf(fmaxf(qc, 1.0f), 255.0f);
}

__device__ __forceinline__ float clip255(float v) {
    return fminf(fmaxf(v, 0.0f), 255.0f);
}

// Reference-exact K=8 dot on float4 halves.
__device__ __forceinline__ float dot8v(float4 a0, float4 a1, float4 b0, float4 b1) {
    float c0 = __fmaf_rn(a1.x, b1.x, __fmul_rn(a0.x, b0.x));
    float c1 = __fmaf_rn(a1.y, b1.y, __fmul_rn(a0.y, b0.y));
    float c2 = __fmaf_rn(a1.z, b1.z, __fmul_rn(a0.z, b0.z));
    float c3 = __fmaf_rn(a1.w, b1.w, __fmul_rn(a0.w, b0.w));
    return __fadd_rn(__fadd_rn(c0, c1), __fadd_rn(c2, c3));
}

#define NT 4          // tiles per CTA
#define BSTR 104      // block stride in floats - bank skew
#define TSTR (6 * BSTR)

__global__ __launch_bounds__(256, 5)
void ela_kernel(const float* __restrict__ in, float* __restrict__ out) {
    __shared__ __align__(16) float sD[8][12];
    __shared__ __align__(16) float sDT[8][12];
    __shared__ float sQY[64];
    __shared__ float sQC[64];
    __shared__ float sLUT[256];                     // n/255 exact
    __shared__ __align__(16) float buf[NT * TSTR];  // B^T -> coef^T -> rec

    const int tid = threadIdx.x;
    sLUT[tid] = __fdiv_rn((float)tid, 255.0f);
    if (tid < 64) {
        int rI = tid >> 3, cI = tid & 7;
        float d = gD[tid];
        sD[rI][cI] = d;
        sDT[cI][rI] = d;
        sQY[tid] = gQY[tid];
        sQC[tid] = gQC[tid];
    }

    const int tx = tid & 15;
    const int ty = tid >> 4;
    const int yblk = ((ty >> 3) << 1) + (tx >> 3);
    const unsigned gy = blockIdx.y * 16 + ty;
    const unsigned rowbase = ((blockIdx.z * 256u + gy) * 256u + blockIdx.x * 64u + tx) * 3u;
    const bool cwrite = ((tx & 1) | (ty & 1)) == 0;

    // ---- pixel phase: load, u8-quantize, RGB->YCbCr, stage Y^T + chroma ----
    #pragma unroll
    for (int t = 0; t < NT; t++) {
        unsigned base = rowbase + t * 48u;
        float r = floorf(clip255(__fmul_rn(in[base + 0], 255.0f)));
        float g = floorf(clip255(__fmul_rn(in[base + 1], 255.0f)));
        float b = floorf(clip255(__fmul_rn(in[base + 2], 255.0f)));

        float Yv = __fadd_rn(__fadd_rn(__fmul_rn(0.299f, r), __fmul_rn(0.587f, g)),
                             __fmul_rn(0.114f, b));
        Yv = clip255(rintf(Yv));
        float Cb = __fadd_rn(__fadd_rn(__fadd_rn(__fmul_rn(-0.168736f, r),
                                                 __fmul_rn(-0.331264f, g)),
                                       __fmul_rn(0.5f, b)), 128.0f);
        Cb = clip255(rintf(Cb));
        float Cr = __fadd_rn(__fadd_rn(__fadd_rn(__fmul_rn(0.5f, r),
                                                 __fmul_rn(-0.418688f, g)),
                                       __fmul_rn(-0.081312f, b)), 128.0f);
        Cr = clip255(rintf(Cr));

        buf[t * TSTR + yblk * BSTR + (tx & 7) * 12 + (ty & 7)] = __fadd_rn(Yv, -128.0f);

        float s1b = __fadd_rn(Cb, __shfl_xor_sync(0xffffffffu, Cb, 1));
        float s1r = __fadd_rn(Cr, __shfl_xor_sync(0xffffffffu, Cr, 1));
        float s2b = __fadd_rn(s1b, __shfl_xor_sync(0xffffffffu, s1b, 16));
        float s2r = __fadd_rn(s1r, __shfl_xor_sync(0xffffffffu, s1r, 16));
        if (cwrite) {
            int j = tx >> 1, i = ty >> 1;
            buf[t * TSTR + 4 * BSTR + j * 12 + i] =
                __fadd_rn(rintf(__fmul_rn(s2b, 0.25f)), -128.0f);
            buf[t * TSTR + 5 * BSTR + j * 12 + i] =
                __fadd_rn(rintf(__fmul_rn(s2r, 0.25f)), -128.0f);
        }
    }
    __syncthreads();

    // ---- DCT phase: PACKED — threads 0..191, 48 per tile, 8-lane blocks ----
    const bool active = tid < 48 * NT;
    const int dt  = tid / 48;
    const int loc = tid - dt * 48;
    const int dblk = loc >> 3;
    const int drr  = loc & 7;
    float* blkbase = &buf[dt * TSTR + dblk * BSTR];

    float m[8];

    // stage A-1: M1 row = D[drr] . B^T rows
    if (active) {
        float4 a0 = *(const float4*)&sD[drr][0];
        float4 a1 = *(const float4*)&sD[drr][4];
        #pragma unroll
        for (int c = 0; c < 8; c++) {
            float4 b0 = *(const float4*)&blkbase[c * 12];
            float4 b1 = *(const float4*)&blkbase[c * 12 + 4];
            m[c] = dot8v(a0, a1, b0, b1);
        }
    }
    __syncwarp();
    // stage A-2: coef row = M1 row . D rows; quantize; store coef^T in-place
    if (active) {
        float4 m0 = make_float4(m[0], m[1], m[2], m[3]);
        float4 m1 = make_float4(m[4], m[5], m[6], m[7]);
        const float* Q = (dblk < 4) ? sQY : sQC;
        #pragma unroll
        for (int c = 0; c < 8; c++) {
            float4 d0 = *(const float4*)&sD[c][0];
            float4 d1 = *(const float4*)&sD[c][4];
            float acc = dot8v(m0, m1, d0, d1);
            float q = Q[drr * 8 + c];
            blkbase[c * 12 + drr] = __fmul_rn(rintf(__fdiv_rn(acc, q)), q);
        }
    }
    __syncwarp();
    // stage B-1: M2 row = D^T[drr] . coef^T rows
    if (active) {
        float4 a0 = *(const float4*)&sDT[drr][0];
        float4 a1 = *(const float4*)&sDT[drr][4];
        #pragma unroll
        for (int c = 0; c < 8; c++) {
            float4 b0 = *(const float4*)&blkbase[c * 12];
            float4 b1 = *(const float4*)&blkbase[c * 12 + 4];
            m[c] = dot8v(a0, a1, b0, b1);
        }
    }
    __syncwarp();
    // stage B-2: rec row = M2 row . D^T rows; store row-major
    if (active) {
        float4 m0 = make_float4(m[0], m[1], m[2], m[3]);
        float4 m1 = make_float4(m[4], m[5], m[6], m[7]);
        float o[8];
        #pragma unroll
        for (int c = 0; c < 8; c++) {
            float4 d0 = *(const float4*)&sDT[c][0];
            float4 d1 = *(const float4*)&sDT[c][4];
            float acc = dot8v(m0, m1, d0, d1);
            o[c] = clip255(rintf(__fadd_rn(acc, 128.0f)));
        }
        float4* orow = (float4*)&blkbase[drr * 12];
        orow[0] = make_float4(o[0], o[1], o[2], o[3]);
        orow[1] = make_float4(o[4], o[5], o[6], o[7]);
    }
    __syncthreads();

    // ---- final: re-read input (L1-hit), decode, ELA via LUT, store ----
    #pragma unroll
    for (int t = 0; t < NT; t++) {
        unsigned base = rowbase + t * 48u;
        float r = floorf(clip255(__fmul_rn(in[base + 0], 255.0f)));
        float g = floorf(clip255(__fmul_rn(in[base + 1], 255.0f)));
        float b = floorf(clip255(__fmul_rn(in[base + 2], 255.0f)));

        float Yd  = buf[t * TSTR + yblk * BSTR + (ty & 7) * 12 + (tx & 7)];
        float Cbd = __fadd_rn(buf[t * TSTR + 4 * BSTR + (ty >> 1) * 12 + (tx >> 1)], -128.0f);
        float Crd = __fadd_rn(buf[t * TSTR + 5 * BSTR + (ty >> 1) * 12 + (tx >> 1)], -128.0f);

        float Rd = __fadd_rn(Yd, __fmul_rn(1.402f, Crd));
        float Gd = __fadd_rn(__fadd_rn(Yd, -__fmul_rn(0.344136f, Cbd)),
                             -__fmul_rn(0.714136f, Crd));
        float Bd = __fadd_rn(Yd, __fmul_rn(1.772f, Cbd));

        float decR = clip255(rintf(Rd));
        float decG = clip255(rintf(Gd));
        float decB = clip255(rintf(Bd));

        out[base + 0] = sLUT[__float2int_rn(fabsf(__fadd_rn(r, -decR)))];
        out[base + 1] = sLUT[__float2int_rn(fabsf(__fadd_rn(g, -decG)))];
        out[base + 2] = sLUT[__float2int_rn(fabsf(__fadd_rn(b, -decB)))];
    }
}

extern "C" void kernel_launch(void* const* d_in, const int* in_sizes, int n_in,
                              void* d_out, int out_size) {
    const float* in = (const float*)d_in[0];
    float* out = (float*)d_out;
    int B = in_sizes[0] / (256 * 256 * 3);

    ela_init_tables<<<1, 64>>>();
    dim3 grid(4, 16, B);
    ela_kernel<<<grid, 256>>>(in, out);
}